// round 14
// baseline (speedup 1.0000x reference)
#include <cuda_runtime.h>
#include <cuda_bf16.h>
#include <math.h>
#include <stdint.h>

// ---------------- problem constants ----------------
#define BATCH 64
#define SEQ   64
#define EMB   256
#define UNITS 512
#define GRU   256
#define FC    1024
#define VOCAB 50000

// ---------------- scratch (device globals; no allocation allowed) ----------------
__device__ float g_hidproj[BATCH * UNITS];
__device__ float g_qp[BATCH * SEQ * UNITS];
__device__ float g_score[BATCH * SEQ];
__device__ float g_gx[BATCH * 2 * EMB];
__device__ float g_fcin[BATCH * (GRU + UNITS)];
__device__ float g_t1[BATCH * FC];
__device__ float g_t2[BATCH * FC];
__device__ float g_part[4 * BATCH * FC];
__device__ float g_qsdup[EMB * 2 * (BATCH * SEQ)];   // qs^T duplicated: [256][8192]
__device__ float g_t2dup[FC * 2 * BATCH];            // t2^T duplicated: [1024][128]

// ---------------- packed dual-fp32 FMA (B300 FFMA2) ----------------
__device__ __forceinline__ uint64_t ffma2(uint64_t a, uint64_t b, uint64_t c) {
    uint64_t d;
    asm("fma.rn.f32x2 %0, %1, %2, %3;" : "=l"(d) : "l"(a), "l"(b), "l"(c));
    return d;
}
__device__ __forceinline__ uint64_t dup2(float x) {
    uint64_t d; uint32_t u = __float_as_uint(x);
    asm("mov.b64 %0, {%1, %1};" : "=l"(d) : "r"(u));
    return d;
}
__device__ __forceinline__ uint32_t smem_u32(const void* p) {
    uint32_t a;
    asm("{ .reg .u64 t; cvta.to.shared.u64 t, %1; cvt.u32.u64 %0, t; }" : "=r"(a) : "l"(p));
    return a;
}
__device__ __forceinline__ void cp_async16(uint32_t dst, const void* src, uint32_t src_sz) {
    asm volatile("cp.async.ca.shared.global [%0], [%1], 16, %2;"
                 :: "r"(dst), "l"(src), "r"(src_sz) : "memory");
}
#define CP_COMMIT() asm volatile("cp.async.commit_group;" ::: "memory")
#define CP_WAIT1()  asm volatile("cp.async.wait_group 1;" ::: "memory")
#define CP_WAIT0()  asm volatile("cp.async.wait_group 0;" ::: "memory")

// ---------------- dup_k: Adup[k][2m] = Adup[k][2m+1] = A[m][k] ----------------
__global__ __launch_bounds__(256) void dup_k(
    const float* __restrict__ A, float* __restrict__ Adup, int M, int K)
{
    __shared__ float tile[32][33];
    const int tx = threadIdx.x & 31, ty = threadIdx.x >> 5;
    const int k0 = blockIdx.x * 32, m0 = blockIdx.y * 32;
#pragma unroll
    for (int r = 0; r < 4; r++)
        tile[ty + 8 * r][tx] = A[(m0 + ty + 8 * r) * K + k0 + tx];
    __syncthreads();
#pragma unroll
    for (int r = 0; r < 4; r++) {
        float v = tile[tx][ty + 8 * r];
        *(float2*)&Adup[(size_t)(k0 + ty + 8 * r) * (2 * M) + 2 * (m0 + tx)] =
            make_float2(v, v);
    }
}

// ================= gemm_cp: FFMA2 GEMM with cp.async staging =================
// C[M,N] = A[M,K] @ B[K,N] + bias, A given PRE-DUPLICATED as Adup[K][2M].
// CTA tile 64x128, 256 threads, thread tile 8m x (2+2)n at cols {2tx, 64+2tx}.
// Per stage each thread cp.asyncs 4 A-chunks + 4 B-chunks (full 16KB + 16KB).
// All LDS conflict-free. Requires M%64==0, K%32==0, N%4==0.
#define GG_AROW 132
#define GG_ABUF (32 * GG_AROW)           // 4224 floats
#define GG_BBUF (32 * 128)               // 4096 floats
#define GG_SMEM ((2 * (GG_ABUF + GG_BBUF)) * 4)   // 66560 bytes

__global__ __launch_bounds__(256, 3) void gemm_cp(
    const float* __restrict__ Adup, const float* __restrict__ B,
    const float* __restrict__ bias, float* __restrict__ C,
    int M, int N, int K)
{
    extern __shared__ float sm[];
    float* As = sm;                      // [2][32][GG_AROW]
    float* Bs = sm + 2 * GG_ABUF;        // [2][32][128]
    const uint32_t sA = smem_u32(As), sB = smem_u32(Bs);

    const int tid = threadIdx.x, tx = tid & 31, ty = tid >> 5;
    const int n0 = blockIdx.x * 128, m0 = blockIdx.y * 64;
    const int NT = K >> 5, M2 = 2 * M;

    // staging geometry: row = tid>>3 (0..31), chunks c = (tid&7) + 8e, e=0..3
    const int srow = tid >> 3, sc0 = tid & 7;
    uint32_t bsz[4];
#pragma unroll
    for (int e = 0; e < 4; e++) {
        int c = sc0 + 8 * e;
        bsz[e] = (n0 + 4 * c + 4 <= N) ? 16u : 0u;   // N%4==0: no partial chunks
    }

    uint64_t acc[8][2];
#pragma unroll
    for (int i = 0; i < 8; i++) { acc[i][0] = 0ull; acc[i][1] = 0ull; }

    // ---- prologue: stage 0 into buffer 0 ----
    {
        const float* as = Adup + (size_t)srow * M2 + 2 * m0;
        const float* bs = B + (size_t)srow * N + n0;
#pragma unroll
        for (int e = 0; e < 4; e++) {
            int c = sc0 + 8 * e;
            cp_async16(sA + (srow * GG_AROW + c * 4) * 4, as + c * 4, 16u);
            cp_async16(sB + (srow * 128 + c * 4) * 4, bs + c * 4, bsz[e]);
        }
        CP_COMMIT();
    }

    for (int s = 0; s < NT; s++) {
        const int b = s & 1;
        if (s + 1 < NT) {
            const int kb = (s + 1) << 5;
            const int nb = b ^ 1;
            const float* as = Adup + (size_t)(kb + srow) * M2 + 2 * m0;
            const float* bs = B + (size_t)(kb + srow) * N + n0;
#pragma unroll
            for (int e = 0; e < 4; e++) {
                int c = sc0 + 8 * e;
                cp_async16(sA + (nb * GG_ABUF + srow * GG_AROW + c * 4) * 4, as + c * 4, 16u);
                cp_async16(sB + (nb * GG_BBUF + srow * 128 + c * 4) * 4, bs + c * 4, bsz[e]);
            }
            CP_COMMIT();
            CP_WAIT1();
        } else {
            CP_WAIT0();
        }
        __syncthreads();

        const float* Ab = As + b * GG_ABUF + 2 * ty;
        const float* Bb = Bs + b * GG_BBUF + 2 * tx;
#pragma unroll 4
        for (int kk = 0; kk < 32; kk++) {
            uint64_t b0 = *(const uint64_t*)(Bb + kk * 128);
            uint64_t b1 = *(const uint64_t*)(Bb + kk * 128 + 64);
            const float* arow = Ab + kk * GG_AROW;
#pragma unroll
            for (int i = 0; i < 8; i++) {
                uint64_t aa = *(const uint64_t*)(arow + 16 * i);   // broadcast pair
                acc[i][0] = ffma2(aa, b0, acc[i][0]);
                acc[i][1] = ffma2(aa, b1, acc[i][1]);
            }
        }
        __syncthreads();   // protect buffer b before re-staging
    }

    // ---- epilogue: two coalesced STG.64 per row ----
    const int n1 = n0 + 2 * tx, n2 = n0 + 64 + 2 * tx;
    float2 bv1 = (n1 < N) ? *(const float2*)&bias[n1] : make_float2(0.f, 0.f);
    float2 bv2 = (n2 < N) ? *(const float2*)&bias[n2] : make_float2(0.f, 0.f);
#pragma unroll
    for (int i = 0; i < 8; i++) {
        int m = m0 + ty + 8 * i;
        if (n1 < N) {
            float2 p = *(float2*)&acc[i][0];
            *(float2*)&C[(size_t)m * N + n1] = make_float2(p.x + bv1.x, p.y + bv1.y);
        }
        if (n2 < N) {
            float2 p = *(float2*)&acc[i][1];
            *(float2*)&C[(size_t)m * N + n2] = make_float2(p.x + bv2.x, p.y + bv2.y);
        }
    }
}

// ================= dense8_ks: batch-tiled (8) + K-split dense partials ==========
__global__ __launch_bounds__(256) void dense8_ks(
    const float* __restrict__ in, const float* __restrict__ W,
    float* __restrict__ part, int IN, int OUT, int KC)
{
    extern __shared__ float ins[];
    const int o = blockIdx.x * 256 + threadIdx.x;
    const int bg = blockIdx.y * 8;
    const int kbase = blockIdx.z * KC;

#pragma unroll
    for (int bb = 0; bb < 8; bb++)
        for (int k = threadIdx.x; k < KC; k += 256)
            ins[k * 10 + bb] = in[(bg + bb) * IN + kbase + k];
    __syncthreads();

    uint64_t acc[4] = {0ull, 0ull, 0ull, 0ull};
    const float* Wp = W + (size_t)kbase * OUT + o;
#pragma unroll 8
    for (int k = 0; k < KC; k++) {
        uint64_t ww = dup2(Wp[(size_t)k * OUT]);
        const uint64_t* ip = (const uint64_t*)&ins[k * 10];
        acc[0] = ffma2(ww, ip[0], acc[0]);
        acc[1] = ffma2(ww, ip[1], acc[1]);
        acc[2] = ffma2(ww, ip[2], acc[2]);
        acc[3] = ffma2(ww, ip[3], acc[3]);
    }
    float* pp = part + ((size_t)blockIdx.z * BATCH + bg) * OUT + o;
#pragma unroll
    for (int j = 0; j < 4; j++) {
        float2 p = *(float2*)&acc[j];
        pp[(2 * j) * OUT] = p.x;
        pp[(2 * j + 1) * OUT] = p.y;
    }
}

// ---------------- finisher ----------------
__global__ __launch_bounds__(256) void fin_k(
    const float* __restrict__ part, const float* __restrict__ bias,
    float* __restrict__ out, int OUT, int KS)
{
    int i = blockIdx.x * 256 + threadIdx.x;
    float s = bias[i % OUT];
    for (int c = 0; c < KS; c++) s += part[c * BATCH * OUT + i];
    out[i] = s;
}

// ---------------- GRU finisher (h0 = 0) ----------------
__global__ __launch_bounds__(256) void gru_fin(
    const float* __restrict__ part, const float* __restrict__ bg,
    const float* __restrict__ features,
    float* __restrict__ state_out, float* __restrict__ fc_in)
{
    const int b = blockIdx.x, g = threadIdx.x;
    float mz = 0.f, mr = 0.f, mh = 0.f;
#pragma unroll
    for (int c = 0; c < 4; c++) {
        const float* p = part + (c * BATCH + b) * (3 * GRU);
        mz += p[g]; mr += p[GRU + g]; mh += p[2 * GRU + g];
    }
    mz += bg[g]; mr += bg[GRU + g]; mh += bg[2 * GRU + g];
    const float* bgh = bg + 3 * GRU;
    float z = 1.f / (1.f + expf(-(mz + bgh[g])));
    float r = 1.f / (1.f + expf(-(mr + bgh[GRU + g])));
    float hc = tanhf(mh + r * bgh[2 * GRU + g]);
    float st = (1.f - z) * hc;
    state_out[b * GRU + g] = st;
    fc_in[b * (GRU + UNITS) + g] = st;
    fc_in[b * (GRU + UNITS) + GRU + g] = features[b * UNITS + g];
    fc_in[b * (GRU + UNITS) + GRU + 256 + g] = features[b * UNITS + 256 + g];
}

// ---------------- attention score ----------------
__global__ __launch_bounds__(256) void score_k(
    const float* __restrict__ qp, const float* __restrict__ hidproj,
    const float* __restrict__ V, const float* __restrict__ bV,
    float* __restrict__ score)
{
    int bs = blockIdx.x, b = bs >> 6, t = threadIdx.x;
    const float* qrow = qp + bs * UNITS;
    const float* hp = hidproj + b * UNITS;
    float s = 0.f;
    for (int u = t; u < UNITS; u += 256)
        s += tanhf(qrow[u] + hp[u]) * V[u];
    __shared__ float red[256];
    red[t] = s; __syncthreads();
    for (int o = 128; o > 0; o >>= 1) {
        if (t < o) red[t] += red[t + o];
        __syncthreads();
    }
    if (t == 0) score[bs] = red[0] + bV[0];
}

// ---------------- softmax + context + embedding ----------------
__global__ __launch_bounds__(64) void softctx_k(
    const float* __restrict__ score, const float* __restrict__ qs,
    const int* __restrict__ x, const float* __restrict__ E,
    float* __restrict__ weights_out, float* __restrict__ gx)
{
    int b = blockIdx.y, part = blockIdx.x, t = threadIdx.x;
    __shared__ float w[SEQ];
    w[t] = score[b * SEQ + t];
    __syncthreads();
    if (t < 32) {
        float a0 = w[t], a1 = w[t + 32];
        float m = fmaxf(a0, a1);
#pragma unroll
        for (int o = 16; o; o >>= 1) m = fmaxf(m, __shfl_xor_sync(0xffffffff, m, o));
        float e0 = expf(a0 - m), e1 = expf(a1 - m);
        float s = e0 + e1;
#pragma unroll
        for (int o = 16; o; o >>= 1) s += __shfl_xor_sync(0xffffffff, s, o);
        float inv = 1.f / s;
        w[t] = e0 * inv; w[t + 32] = e1 * inv;
    }
    __syncthreads();
    if (part == 0) weights_out[b * SEQ + t] = w[t];
    int e = part * 64 + t;
    float c = 0.f;
#pragma unroll 8
    for (int s2 = 0; s2 < SEQ; s2++)
        c = fmaf(w[s2], qs[(b * SEQ + s2) * EMB + e], c);
    gx[b * 2 * EMB + EMB + e] = c;
    gx[b * 2 * EMB + e] = E[x[b] * EMB + e];
}

// ---------------- launch ----------------
extern "C" void kernel_launch(void* const* d_in, const int* in_sizes, int n_in,
                              void* d_out, int out_size)
{
    const int*   x        = (const int*)  d_in[0];
    const float* qs       = (const float*)d_in[1];
    const float* features = (const float*)d_in[2];
    const float* hidden   = (const float*)d_in[3];
    const float* E        = (const float*)d_in[4];
    const float* W1       = (const float*)d_in[5];
    const float* b1       = (const float*)d_in[6];
    const float* W2       = (const float*)d_in[7];
    const float* b2       = (const float*)d_in[8];
    const float* V        = (const float*)d_in[9];
    const float* bV       = (const float*)d_in[10];
    const float* Kg       = (const float*)d_in[11];
    /* d_in[12] = Ug dead (h0 == 0) */
    const float* bg       = (const float*)d_in[13];
    const float* Wf1      = (const float*)d_in[14];
    const float* bf1      = (const float*)d_in[15];
    const float* Wf2      = (const float*)d_in[16];
    const float* bf2      = (const float*)d_in[17];
    const float* Wo       = (const float*)d_in[18];
    const float* bo       = (const float*)d_in[19];

    float* out = (float*)d_out;
    float* logits      = out;
    float* state_out   = out + BATCH * VOCAB;
    float* weights_out = state_out + BATCH * GRU;

    float *hidproj, *qp, *score, *gx, *fcin, *t1, *t2, *part, *qsdup, *t2dup;
    cudaGetSymbolAddress((void**)&hidproj, g_hidproj);
    cudaGetSymbolAddress((void**)&qp,      g_qp);
    cudaGetSymbolAddress((void**)&score,   g_score);
    cudaGetSymbolAddress((void**)&gx,      g_gx);
    cudaGetSymbolAddress((void**)&fcin,    g_fcin);
    cudaGetSymbolAddress((void**)&t1,      g_t1);
    cudaGetSymbolAddress((void**)&t2,      g_t2);
    cudaGetSymbolAddress((void**)&part,    g_part);
    cudaGetSymbolAddress((void**)&qsdup,   g_qsdup);
    cudaGetSymbolAddress((void**)&t2dup,   g_t2dup);

    cudaFuncSetAttribute(gemm_cp, cudaFuncAttributeMaxDynamicSharedMemorySize, GG_SMEM);

    // 1-2: hidden @ W2 + b2
    dense8_ks<<<dim3(UNITS / 256, BATCH / 8, 4), 256, 128 * 10 * 4>>>(
        hidden, W2, part, UNITS, UNITS, 128);
    fin_k<<<BATCH * UNITS / 256, 256>>>(part, b2, hidproj, UNITS, 4);
    // 3: duplicate-transpose qs  [4096,256] -> [256][8192]
    dup_k<<<dim3(EMB / 32, (BATCH * SEQ) / 32), 256>>>(qs, qsdup, BATCH * SEQ, EMB);
    // 4 (PROFILED): qs @ W1 + b1
    gemm_cp<<<dim3(UNITS / 128, (BATCH * SEQ) / 64), 256, GG_SMEM>>>(
        qsdup, W1, b1, qp, BATCH * SEQ, UNITS, EMB);
    // 5-6: score + softmax/context/embed
    score_k<<<BATCH * SEQ, 256>>>(qp, hidproj, V, bV, score);
    softctx_k<<<dim3(4, BATCH), 64>>>(score, qs, x, E, weights_out, gx);
    // 7-8: GRU
    dense8_ks<<<dim3(3 * GRU / 256, BATCH / 8, 4), 256, 128 * 10 * 4>>>(
        gx, Kg, part, 2 * EMB, 3 * GRU, 128);
    gru_fin<<<BATCH, GRU>>>(part, bg, features, state_out, fcin);
    // 9-12: fc stack
    dense8_ks<<<dim3(FC / 256, BATCH / 8, 4), 256, 192 * 10 * 4>>>(
        fcin, Wf1, part, GRU + UNITS, FC, 192);
    fin_k<<<BATCH * FC / 256, 256>>>(part, bf1, t1, FC, 4);
    dense8_ks<<<dim3(FC / 256, BATCH / 8, 4), 256, 256 * 10 * 4>>>(
        t1, Wf2, part, FC, FC, 256);
    fin_k<<<BATCH * FC / 256, 256>>>(part, bf2, t2, FC, 4);
    // 13: duplicate-transpose t2  [64,1024] -> [1024][128]
    dup_k<<<dim3(FC / 32, BATCH / 32), 256>>>(t2, t2dup, BATCH, FC);
    // 14: logits GEMM  [64,50000] = t2 @ Wo + bo
    gemm_cp<<<dim3((VOCAB + 127) / 128, 1), 256, GG_SMEM>>>(
        t2dup, Wo, bo, logits, BATCH, VOCAB, FC);
}

// round 15
// speedup vs baseline: 1.0377x; 1.0377x over previous
#include <cuda_runtime.h>
#include <cuda_bf16.h>
#include <math.h>
#include <stdint.h>

// ---------------- problem constants ----------------
#define BATCH 64
#define SEQ   64
#define EMB   256
#define UNITS 512
#define GRU   256
#define FC    1024
#define VOCAB 50000

// ---------------- scratch (device globals; no allocation allowed) ----------------
__device__ float g_hidproj[BATCH * UNITS];
__device__ float g_qp[BATCH * SEQ * UNITS];
__device__ float g_score[BATCH * SEQ];
__device__ float g_gx[BATCH * 2 * EMB];
__device__ float g_fcin[BATCH * (GRU + UNITS)];
__device__ float g_t1[BATCH * FC];
__device__ float g_t2[BATCH * FC];
__device__ float g_part[4 * BATCH * FC];
__device__ float g_qsdup[EMB * 2 * (BATCH * SEQ)];   // qs dup2 layout: [K/2][4M]
__device__ float g_t2dup[FC * 2 * BATCH];            // t2 dup2 layout: [K/2][4M]

// ---------------- packed dual-fp32 FMA (B300 FFMA2) ----------------
__device__ __forceinline__ uint64_t ffma2(uint64_t a, uint64_t b, uint64_t c) {
    uint64_t d;
    asm("fma.rn.f32x2 %0, %1, %2, %3;" : "=l"(d) : "l"(a), "l"(b), "l"(c));
    return d;
}
__device__ __forceinline__ uint64_t dup2(float x) {
    uint64_t d; uint32_t u = __float_as_uint(x);
    asm("mov.b64 %0, {%1, %1};" : "=l"(d) : "r"(u));
    return d;
}
__device__ __forceinline__ uint32_t smem_u32(const void* p) {
    uint32_t a;
    asm("{ .reg .u64 t; cvta.to.shared.u64 t, %1; cvt.u32.u64 %0, t; }" : "=r"(a) : "l"(p));
    return a;
}
__device__ __forceinline__ void cp_async16(uint32_t dst, const void* src, uint32_t src_sz) {
    asm volatile("cp.async.ca.shared.global [%0], [%1], 16, %2;"
                 :: "r"(dst), "l"(src), "r"(src_sz) : "memory");
}
#define CP_COMMIT() asm volatile("cp.async.commit_group;" ::: "memory")
#define CP_WAIT1()  asm volatile("cp.async.wait_group 1;" ::: "memory")
#define CP_WAIT0()  asm volatile("cp.async.wait_group 0;" ::: "memory")

// ---------------- dup_k2: Adup[k/2][4m + 2(k&1) + {0,1}] = A[m][k] ----------------
// Interleaved-duplicated transpose: one 16B at [k2][4m] = {a[2k2][m] x2, a[2k2+1][m] x2}.
// Requires M%32==0, K%32==0.
__global__ __launch_bounds__(256) void dup_k2(
    const float* __restrict__ A, float* __restrict__ Adup, int M, int K)
{
    __shared__ float tile[32][33];
    const int tx = threadIdx.x & 31, ty = threadIdx.x >> 5;
    const int k0 = blockIdx.x * 32, m0 = blockIdx.y * 32;
#pragma unroll
    for (int r = 0; r < 4; r++)
        tile[ty + 8 * r][tx] = A[(size_t)(m0 + ty + 8 * r) * K + k0 + tx];
    __syncthreads();
    const size_t M4 = 4 * (size_t)M;
#pragma unroll
    for (int r = 0; r < 4; r++) {
        int kk = ty + 8 * r;                      // local k
        float v = tile[tx][kk];                   // A[m0+tx][k0+kk]
        size_t off = (size_t)((k0 + kk) >> 1) * M4 + 4 * (m0 + tx) + 2 * (kk & 1);
        *(float2*)&Adup[off] = make_float2(v, v);
    }
}

// ================= gemm_cp2: FFMA2 GEMM, 5 LDS.128 + 16 FFMA2 per kk =================
// C[M,N] = A[M,K] @ B[K,N] + bias, A given in dup2 layout [K/2][4M].
// CTA tile 64x128, 256 threads, thread tile 8m x 4n (cols 4tx..4tx+3).
// Per k2 (2 k's): 8 broadcast LDS.128 (A) + 2 LDS.128 (B) + 32 FFMA2.
// Requires M%64==0, K%32==0, N%4==0.
#define GG_APITCH 260                    // floats per A k2-row (1040B, 16B-aligned)
#define GG_ABUF (16 * GG_APITCH)         // 4160 floats per buffer
#define GG_BBUF (32 * 128)               // 4096 floats per buffer
#define GG_SMEM ((2 * (GG_ABUF + GG_BBUF)) * 4)   // 66048 bytes

__global__ __launch_bounds__(256, 3) void gemm_cp(
    const float* __restrict__ Adup, const float* __restrict__ B,
    const float* __restrict__ bias, float* __restrict__ C,
    int M, int N, int K)
{
    extern __shared__ float sm[];
    float* As = sm;                      // [2][16][GG_APITCH]
    float* Bs = sm + 2 * GG_ABUF;        // [2][32][128]
    const uint32_t sA = smem_u32(As), sB = smem_u32(Bs);

    const int tid = threadIdx.x, tx = tid & 31, ty = tid >> 5;
    const int n0 = blockIdx.x * 128, m0 = blockIdx.y * 64;
    const int NT = K >> 5;
    const size_t M4 = 4 * (size_t)M;

    // A staging: rows ra = (tid>>6) + 4e (k2-rows 0..15), col-chunk ca = tid&63
    const int ra0 = tid >> 6, ca = tid & 63;
    // B staging: rows rb = (tid>>5) + 8e (k-rows 0..31), col-chunk cb = tid&31
    const int rb0 = tid >> 5, cb = tid & 31;
    const uint32_t bsz = (n0 + cb * 4 + 4 <= N) ? 16u : 0u;

    uint64_t acc[8][2];
#pragma unroll
    for (int i = 0; i < 8; i++) { acc[i][0] = 0ull; acc[i][1] = 0ull; }

    // ---- prologue: stage 0 into buffer 0 ----
    {
        const float* abase = Adup + (size_t)ra0 * M4 + 4 * m0 + ca * 4;
        const float* bbase = B + (size_t)rb0 * N + n0 + cb * 4;
#pragma unroll
        for (int e = 0; e < 4; e++) {
            cp_async16(sA + ((ra0 + 4 * e) * GG_APITCH + ca * 4) * 4,
                       abase + (size_t)(4 * e) * M4, 16u);
            cp_async16(sB + ((rb0 + 8 * e) * 128 + cb * 4) * 4,
                       bbase + (size_t)(8 * e) * N, bsz);
        }
        CP_COMMIT();
    }

    for (int s = 0; s < NT; s++) {
        const int b = s & 1;
        if (s + 1 < NT) {
            const int nb = b ^ 1;
            const int kb2 = (s + 1) * 16, kb = (s + 1) * 32;
            const float* abase = Adup + (size_t)(kb2 + ra0) * M4 + 4 * m0 + ca * 4;
            const float* bbase = B + (size_t)(kb + rb0) * N + n0 + cb * 4;
#pragma unroll
            for (int e = 0; e < 4; e++) {
                cp_async16(sA + (nb * GG_ABUF + (ra0 + 4 * e) * GG_APITCH + ca * 4) * 4,
                           abase + (size_t)(4 * e) * M4, 16u);
                cp_async16(sB + (nb * GG_BBUF + (rb0 + 8 * e) * 128 + cb * 4) * 4,
                           bbase + (size_t)(8 * e) * N, bsz);
            }
            CP_COMMIT();
            CP_WAIT1();
        } else {
            CP_WAIT0();
        }
        __syncthreads();

        const float* Ab = As + b * GG_ABUF + 4 * ty;   // + 32*i for m = ty+8i
        const float* Bb = Bs + b * GG_BBUF + 4 * tx;
#pragma unroll 4
        for (int k2 = 0; k2 < 16; k2++) {
            ulonglong2 bev = *(const ulonglong2*)(Bb + (2 * k2) * 128);
            ulonglong2 bov = *(const ulonglong2*)(Bb + (2 * k2 + 1) * 128);
            const float* arow = Ab + k2 * GG_APITCH;
#pragma unroll
            for (int i = 0; i < 8; i++) {
                ulonglong2 av = *(const ulonglong2*)(arow + 32 * i);  // {even pair, odd pair}
                acc[i][0] = ffma2(av.x, bev.x, acc[i][0]);
                acc[i][1] = ffma2(av.x, bev.y, acc[i][1]);
                acc[i][0] = ffma2(av.y, bov.x, acc[i][0]);
                acc[i][1] = ffma2(av.y, bov.y, acc[i][1]);
            }
        }
        __syncthreads();   // protect buffer b before re-staging
    }

    // ---- epilogue: STG.128 per row (N%4==0 -> no partial chunks) ----
    const int n = n0 + 4 * tx;
    if (n < N) {
        float4 bv = *(const float4*)&bias[n];
#pragma unroll
        for (int i = 0; i < 8; i++) {
            int m = m0 + ty + 8 * i;
            float2 p0 = *(float2*)&acc[i][0];
            float2 p1 = *(float2*)&acc[i][1];
            float4 o = make_float4(p0.x + bv.x, p0.y + bv.y, p1.x + bv.z, p1.y + bv.w);
            *(float4*)&C[(size_t)m * N + n] = o;
        }
    }
}

// ================= dense8_ks: batch-tiled (8) + K-split dense partials ==========
__global__ __launch_bounds__(256) void dense8_ks(
    const float* __restrict__ in, const float* __restrict__ W,
    float* __restrict__ part, int IN, int OUT, int KC)
{
    extern __shared__ float ins[];
    const int o = blockIdx.x * 256 + threadIdx.x;
    const int bg = blockIdx.y * 8;
    const int kbase = blockIdx.z * KC;

#pragma unroll
    for (int bb = 0; bb < 8; bb++)
        for (int k = threadIdx.x; k < KC; k += 256)
            ins[k * 10 + bb] = in[(bg + bb) * IN + kbase + k];
    __syncthreads();

    uint64_t acc[4] = {0ull, 0ull, 0ull, 0ull};
    const float* Wp = W + (size_t)kbase * OUT + o;
#pragma unroll 8
    for (int k = 0; k < KC; k++) {
        uint64_t ww = dup2(Wp[(size_t)k * OUT]);
        const uint64_t* ip = (const uint64_t*)&ins[k * 10];
        acc[0] = ffma2(ww, ip[0], acc[0]);
        acc[1] = ffma2(ww, ip[1], acc[1]);
        acc[2] = ffma2(ww, ip[2], acc[2]);
        acc[3] = ffma2(ww, ip[3], acc[3]);
    }
    float* pp = part + ((size_t)blockIdx.z * BATCH + bg) * OUT + o;
#pragma unroll
    for (int j = 0; j < 4; j++) {
        float2 p = *(float2*)&acc[j];
        pp[(2 * j) * OUT] = p.x;
        pp[(2 * j + 1) * OUT] = p.y;
    }
}

// ---------------- finisher ----------------
__global__ __launch_bounds__(256) void fin_k(
    const float* __restrict__ part, const float* __restrict__ bias,
    float* __restrict__ out, int OUT, int KS)
{
    int i = blockIdx.x * 256 + threadIdx.x;
    float s = bias[i % OUT];
    for (int c = 0; c < KS; c++) s += part[c * BATCH * OUT + i];
    out[i] = s;
}

// ---------------- GRU finisher (h0 = 0) ----------------
__global__ __launch_bounds__(256) void gru_fin(
    const float* __restrict__ part, const float* __restrict__ bg,
    const float* __restrict__ features,
    float* __restrict__ state_out, float* __restrict__ fc_in)
{
    const int b = blockIdx.x, g = threadIdx.x;
    float mz = 0.f, mr = 0.f, mh = 0.f;
#pragma unroll
    for (int c = 0; c < 4; c++) {
        const float* p = part + (c * BATCH + b) * (3 * GRU);
        mz += p[g]; mr += p[GRU + g]; mh += p[2 * GRU + g];
    }
    mz += bg[g]; mr += bg[GRU + g]; mh += bg[2 * GRU + g];
    const float* bgh = bg + 3 * GRU;
    float z = 1.f / (1.f + expf(-(mz + bgh[g])));
    float r = 1.f / (1.f + expf(-(mr + bgh[GRU + g])));
    float hc = tanhf(mh + r * bgh[2 * GRU + g]);
    float st = (1.f - z) * hc;
    state_out[b * GRU + g] = st;
    fc_in[b * (GRU + UNITS) + g] = st;
    fc_in[b * (GRU + UNITS) + GRU + g] = features[b * UNITS + g];
    fc_in[b * (GRU + UNITS) + GRU + 256 + g] = features[b * UNITS + 256 + g];
}

// ---------------- attention score ----------------
__global__ __launch_bounds__(256) void score_k(
    const float* __restrict__ qp, const float* __restrict__ hidproj,
    const float* __restrict__ V, const float* __restrict__ bV,
    float* __restrict__ score)
{
    int bs = blockIdx.x, b = bs >> 6, t = threadIdx.x;
    const float* qrow = qp + bs * UNITS;
    const float* hp = hidproj + b * UNITS;
    float s = 0.f;
    for (int u = t; u < UNITS; u += 256)
        s += tanhf(qrow[u] + hp[u]) * V[u];
    __shared__ float red[256];
    red[t] = s; __syncthreads();
    for (int o = 128; o > 0; o >>= 1) {
        if (t < o) red[t] += red[t + o];
        __syncthreads();
    }
    if (t == 0) score[bs] = red[0] + bV[0];
}

// ---------------- softmax + context + embedding ----------------
__global__ __launch_bounds__(64) void softctx_k(
    const float* __restrict__ score, const float* __restrict__ qs,
    const int* __restrict__ x, const float* __restrict__ E,
    float* __restrict__ weights_out, float* __restrict__ gx)
{
    int b = blockIdx.y, part = blockIdx.x, t = threadIdx.x;
    __shared__ float w[SEQ];
    w[t] = score[b * SEQ + t];
    __syncthreads();
    if (t < 32) {
        float a0 = w[t], a1 = w[t + 32];
        float m = fmaxf(a0, a1);
#pragma unroll
        for (int o = 16; o; o >>= 1) m = fmaxf(m, __shfl_xor_sync(0xffffffff, m, o));
        float e0 = expf(a0 - m), e1 = expf(a1 - m);
        float s = e0 + e1;
#pragma unroll
        for (int o = 16; o; o >>= 1) s += __shfl_xor_sync(0xffffffff, s, o);
        float inv = 1.f / s;
        w[t] = e0 * inv; w[t + 32] = e1 * inv;
    }
    __syncthreads();
    if (part == 0) weights_out[b * SEQ + t] = w[t];
    int e = part * 64 + t;
    float c = 0.f;
#pragma unroll 8
    for (int s2 = 0; s2 < SEQ; s2++)
        c = fmaf(w[s2], qs[(b * SEQ + s2) * EMB + e], c);
    gx[b * 2 * EMB + EMB + e] = c;
    gx[b * 2 * EMB + e] = E[x[b] * EMB + e];
}

// ---------------- launch ----------------
extern "C" void kernel_launch(void* const* d_in, const int* in_sizes, int n_in,
                              void* d_out, int out_size)
{
    const int*   x        = (const int*)  d_in[0];
    const float* qs       = (const float*)d_in[1];
    const float* features = (const float*)d_in[2];
    const float* hidden   = (const float*)d_in[3];
    const float* E        = (const float*)d_in[4];
    const float* W1       = (const float*)d_in[5];
    const float* b1       = (const float*)d_in[6];
    const float* W2       = (const float*)d_in[7];
    const float* b2       = (const float*)d_in[8];
    const float* V        = (const float*)d_in[9];
    const float* bV       = (const float*)d_in[10];
    const float* Kg       = (const float*)d_in[11];
    /* d_in[12] = Ug dead (h0 == 0) */
    const float* bg       = (const float*)d_in[13];
    const float* Wf1      = (const float*)d_in[14];
    const float* bf1      = (const float*)d_in[15];
    const float* Wf2      = (const float*)d_in[16];
    const float* bf2      = (const float*)d_in[17];
    const float* Wo       = (const float*)d_in[18];
    const float* bo       = (const float*)d_in[19];

    float* out = (float*)d_out;
    float* logits      = out;
    float* state_out   = out + BATCH * VOCAB;
    float* weights_out = state_out + BATCH * GRU;

    float *hidproj, *qp, *score, *gx, *fcin, *t1, *t2, *part, *qsdup, *t2dup;
    cudaGetSymbolAddress((void**)&hidproj, g_hidproj);
    cudaGetSymbolAddress((void**)&qp,      g_qp);
    cudaGetSymbolAddress((void**)&score,   g_score);
    cudaGetSymbolAddress((void**)&gx,      g_gx);
    cudaGetSymbolAddress((void**)&fcin,    g_fcin);
    cudaGetSymbolAddress((void**)&t1,      g_t1);
    cudaGetSymbolAddress((void**)&t2,      g_t2);
    cudaGetSymbolAddress((void**)&part,    g_part);
    cudaGetSymbolAddress((void**)&qsdup,   g_qsdup);
    cudaGetSymbolAddress((void**)&t2dup,   g_t2dup);

    cudaFuncSetAttribute(gemm_cp, cudaFuncAttributeMaxDynamicSharedMemorySize, GG_SMEM);

    // 1-2: hidden @ W2 + b2
    dense8_ks<<<dim3(UNITS / 256, BATCH / 8, 4), 256, 128 * 10 * 4>>>(
        hidden, W2, part, UNITS, UNITS, 128);
    fin_k<<<BATCH * UNITS / 256, 256>>>(part, b2, hidproj, UNITS, 4);
    // 3: dup2-transpose qs  [4096,256] -> [128][16384]
    dup_k2<<<dim3(EMB / 32, (BATCH * SEQ) / 32), 256>>>(qs, qsdup, BATCH * SEQ, EMB);
    // 4 (PROFILED): qs @ W1 + b1
    gemm_cp<<<dim3(UNITS / 128, (BATCH * SEQ) / 64), 256, GG_SMEM>>>(
        qsdup, W1, b1, qp, BATCH * SEQ, UNITS, EMB);
    // 5-6: score + softmax/context/embed
    score_k<<<BATCH * SEQ, 256>>>(qp, hidproj, V, bV, score);
    softctx_k<<<dim3(4, BATCH), 64>>>(score, qs, x, E, weights_out, gx);
    // 7-8: GRU
    dense8_ks<<<dim3(3 * GRU / 256, BATCH / 8, 4), 256, 128 * 10 * 4>>>(
        gx, Kg, part, 2 * EMB, 3 * GRU, 128);
    gru_fin<<<BATCH, GRU>>>(part, bg, features, state_out, fcin);
    // 9-12: fc stack
    dense8_ks<<<dim3(FC / 256, BATCH / 8, 4), 256, 192 * 10 * 4>>>(
        fcin, Wf1, part, GRU + UNITS, FC, 192);
    fin_k<<<BATCH * FC / 256, 256>>>(part, bf1, t1, FC, 4);
    dense8_ks<<<dim3(FC / 256, BATCH / 8, 4), 256, 256 * 10 * 4>>>(
        t1, Wf2, part, FC, FC, 256);
    fin_k<<<BATCH * FC / 256, 256>>>(part, bf2, t2, FC, 4);
    // 13: dup2-transpose t2  [64,1024] -> [512][256]
    dup_k2<<<dim3(FC / 32, BATCH / 32), 256>>>(t2, t2dup, BATCH, FC);
    // 14: logits GEMM  [64,50000] = t2 @ Wo + bo
    gemm_cp<<<dim3((VOCAB + 127) / 128, 1), 256, GG_SMEM>>>(
        t2dup, Wo, bo, logits, BATCH, VOCAB, FC);
}

// round 16
// speedup vs baseline: 1.4411x; 1.3888x over previous
#include <cuda_runtime.h>
#include <cuda_bf16.h>
#include <math.h>
#include <stdint.h>

// ---------------- problem constants ----------------
#define BATCH 64
#define SEQ   64
#define EMB   256
#define UNITS 512
#define GRU   256
#define FC    1024
#define VOCAB 50000

// ---------------- scratch (device globals; no allocation allowed) ----------------
__device__ float g_hidproj[BATCH * UNITS];
__device__ float g_qp[BATCH * SEQ * UNITS];
__device__ float g_score[BATCH * SEQ];
__device__ float g_gx[BATCH * 2 * EMB];
__device__ float g_fcin[BATCH * (GRU + UNITS)];
__device__ float g_t1[BATCH * FC];
__device__ float g_t2[BATCH * FC];
__device__ float g_part[8 * BATCH * FC];             // K-split partials (8 x 64 x 1024)
__device__ float g_qsdup[EMB * 2 * (BATCH * SEQ)];   // qs dup2 layout: [K/2][4M]
__device__ float g_t2dup[FC * 2 * BATCH];            // t2 dup2 layout: [K/2][4M]

// ---------------- packed dual-fp32 FMA (B300 FFMA2) ----------------
__device__ __forceinline__ uint64_t ffma2(uint64_t a, uint64_t b, uint64_t c) {
    uint64_t d;
    asm("fma.rn.f32x2 %0, %1, %2, %3;" : "=l"(d) : "l"(a), "l"(b), "l"(c));
    return d;
}
__device__ __forceinline__ uint64_t dup2(float x) {
    uint64_t d; uint32_t u = __float_as_uint(x);
    asm("mov.b64 %0, {%1, %1};" : "=l"(d) : "r"(u));
    return d;
}
__device__ __forceinline__ uint32_t smem_u32(const void* p) {
    uint32_t a;
    asm("{ .reg .u64 t; cvta.to.shared.u64 t, %1; cvt.u32.u64 %0, t; }" : "=r"(a) : "l"(p));
    return a;
}
__device__ __forceinline__ void cp_async16(uint32_t dst, const void* src, uint32_t src_sz) {
    asm volatile("cp.async.ca.shared.global [%0], [%1], 16, %2;"
                 :: "r"(dst), "l"(src), "r"(src_sz) : "memory");
}
#define CP_COMMIT() asm volatile("cp.async.commit_group;" ::: "memory")
#define CP_WAIT1()  asm volatile("cp.async.wait_group 1;" ::: "memory")
#define CP_WAIT0()  asm volatile("cp.async.wait_group 0;" ::: "memory")

// ---------------- dup_k2: Adup[k/2][4m + 2(k&1) + {0,1}] = A[m][k] ----------------
__global__ __launch_bounds__(256) void dup_k2(
    const float* __restrict__ A, float* __restrict__ Adup, int M, int K)
{
    __shared__ float tile[32][33];
    const int tx = threadIdx.x & 31, ty = threadIdx.x >> 5;
    const int k0 = blockIdx.x * 32, m0 = blockIdx.y * 32;
#pragma unroll
    for (int r = 0; r < 4; r++)
        tile[ty + 8 * r][tx] = A[(size_t)(m0 + ty + 8 * r) * K + k0 + tx];
    __syncthreads();
    const size_t M4 = 4 * (size_t)M;
#pragma unroll
    for (int r = 0; r < 4; r++) {
        int kk = ty + 8 * r;
        float v = tile[tx][kk];
        size_t off = (size_t)((k0 + kk) >> 1) * M4 + 4 * (m0 + tx) + 2 * (kk & 1);
        *(float2*)&Adup[off] = make_float2(v, v);
    }
}

// ================= gemm_cp: FFMA2 GEMM, 3-stage cp.async ring, 1 sync/stage ========
// C[M,N] = A[M,K] @ B[K,N] + bias, A in dup2 layout [K/2][4M].
// CTA tile 64x128, 256 threads, thread tile 8m x 4n (cols 4tx..4tx+3).
// Requires M%64==0, K%32==0 (NT>=2), N%4==0.
#define GG_APITCH 260                    // floats per A k2-row (1040B)
#define GG_ABUF (16 * GG_APITCH)         // 4160 floats
#define GG_BBUF (32 * 128)               // 4096 floats
#define GG_STG  (GG_ABUF + GG_BBUF)      // 8256 floats per stage
#define GG_SMEM (3 * GG_STG * 4)         // 99072 bytes

__global__ __launch_bounds__(256, 2) void gemm_cp(
    const float* __restrict__ Adup, const float* __restrict__ B,
    const float* __restrict__ bias, float* __restrict__ C,
    int M, int N, int K)
{
    extern __shared__ float sm[];
    const uint32_t sbase = smem_u32(sm);

    const int tid = threadIdx.x, tx = tid & 31, ty = tid >> 5;
    const int n0 = blockIdx.x * 128, m0 = blockIdx.y * 64;
    const int NT = K >> 5;
    const size_t M4 = 4 * (size_t)M;

    // A staging: k2-rows ra0+4e, col-chunk ca (0..63); B: k-rows rb0+8e, chunk cb
    const int ra0 = tid >> 6, ca = tid & 63;
    const int rb0 = tid >> 5, cb = tid & 31;
    const uint32_t bsz = (n0 + cb * 4 + 4 <= N) ? 16u : 0u;

    uint64_t acc[8][2];
#pragma unroll
    for (int i = 0; i < 8; i++) { acc[i][0] = 0ull; acc[i][1] = 0ull; }

    // ---- stage s into ring slot u ----
    auto stage = [&](int s, int u) {
        const float* abase = Adup + (size_t)(s * 16 + ra0) * M4 + 4 * m0 + ca * 4;
        const float* bbase = B + (size_t)(s * 32 + rb0) * N + n0 + cb * 4;
        const uint32_t sA = sbase + u * (GG_STG * 4);
        const uint32_t sB = sA + GG_ABUF * 4;
#pragma unroll
        for (int e = 0; e < 4; e++) {
            cp_async16(sA + ((ra0 + 4 * e) * GG_APITCH + ca * 4) * 4,
                       abase + (size_t)(4 * e) * M4, 16u);
            cp_async16(sB + ((rb0 + 8 * e) * 128 + cb * 4) * 4,
                       bbase + (size_t)(8 * e) * N, bsz);
        }
        CP_COMMIT();
    };

    // ---- prologue: stages 0, 1 ----
    stage(0, 0);
    stage(1, 1);

    for (int s = 0; s < NT; s++) {
        if (s == NT - 1) { CP_WAIT0(); } else { CP_WAIT1(); }
        __syncthreads();
        const int u = s % 3;
        const float* Ab = sm + u * GG_STG + 4 * ty;
        const float* Bb = sm + u * GG_STG + GG_ABUF + 4 * tx;
#pragma unroll
        for (int k2 = 0; k2 < 16; k2++) {
            ulonglong2 bev = *(const ulonglong2*)(Bb + (2 * k2) * 128);
            ulonglong2 bov = *(const ulonglong2*)(Bb + (2 * k2 + 1) * 128);
            const float* arow = Ab + k2 * GG_APITCH;
#pragma unroll
            for (int i = 0; i < 8; i++) {
                ulonglong2 av = *(const ulonglong2*)(arow + 32 * i);  // {even pair, odd pair}
                acc[i][0] = ffma2(av.x, bev.x, acc[i][0]);
                acc[i][1] = ffma2(av.x, bev.y, acc[i][1]);
                acc[i][0] = ffma2(av.y, bov.x, acc[i][0]);
                acc[i][1] = ffma2(av.y, bov.y, acc[i][1]);
            }
        }
        if (s + 2 < NT) stage(s + 2, (s + 2) % 3);
    }

    // ---- epilogue: STG.128 per row ----
    const int n = n0 + 4 * tx;
    if (n < N) {
        float4 bv = *(const float4*)&bias[n];
#pragma unroll
        for (int i = 0; i < 8; i++) {
            int m = m0 + ty + 8 * i;
            float2 p0 = *(float2*)&acc[i][0];
            float2 p1 = *(float2*)&acc[i][1];
            float4 o = make_float4(p0.x + bv.x, p0.y + bv.y, p1.x + bv.z, p1.y + bv.w);
            *(float4*)&C[(size_t)m * N + n] = o;
        }
    }
}

// ================= dense8_ks: batch-tiled (8) + K-split(8) dense partials ==========
__global__ __launch_bounds__(256) void dense8_ks(
    const float* __restrict__ in, const float* __restrict__ W,
    float* __restrict__ part, int IN, int OUT, int KC)
{
    extern __shared__ float ins[];
    const int o = blockIdx.x * 256 + threadIdx.x;
    const int bg = blockIdx.y * 8;
    const int kbase = blockIdx.z * KC;

#pragma unroll
    for (int bb = 0; bb < 8; bb++)
        for (int k = threadIdx.x; k < KC; k += 256)
            ins[k * 10 + bb] = in[(bg + bb) * IN + kbase + k];
    __syncthreads();

    uint64_t acc[4] = {0ull, 0ull, 0ull, 0ull};
    const float* Wp = W + (size_t)kbase * OUT + o;
#pragma unroll 8
    for (int k = 0; k < KC; k++) {
        uint64_t ww = dup2(Wp[(size_t)k * OUT]);
        const uint64_t* ip = (const uint64_t*)&ins[k * 10];
        acc[0] = ffma2(ww, ip[0], acc[0]);
        acc[1] = ffma2(ww, ip[1], acc[1]);
        acc[2] = ffma2(ww, ip[2], acc[2]);
        acc[3] = ffma2(ww, ip[3], acc[3]);
    }
    float* pp = part + ((size_t)blockIdx.z * BATCH + bg) * OUT + o;
#pragma unroll
    for (int j = 0; j < 4; j++) {
        float2 p = *(float2*)&acc[j];
        pp[(2 * j) * OUT] = p.x;
        pp[(2 * j + 1) * OUT] = p.y;
    }
}

// ---------------- finisher ----------------
__global__ __launch_bounds__(256) void fin_k(
    const float* __restrict__ part, const float* __restrict__ bias,
    float* __restrict__ out, int OUT, int KS)
{
    int i = blockIdx.x * 256 + threadIdx.x;
    float s = bias[i % OUT];
    for (int c = 0; c < KS; c++) s += part[c * BATCH * OUT + i];
    out[i] = s;
}

// ---------------- GRU finisher (h0 = 0) ----------------
__global__ __launch_bounds__(256) void gru_fin(
    const float* __restrict__ part, const float* __restrict__ bg,
    const float* __restrict__ features,
    float* __restrict__ state_out, float* __restrict__ fc_in)
{
    const int b = blockIdx.x, g = threadIdx.x;
    float mz = 0.f, mr = 0.f, mh = 0.f;
#pragma unroll
    for (int c = 0; c < 8; c++) {
        const float* p = part + (c * BATCH + b) * (3 * GRU);
        mz += p[g]; mr += p[GRU + g]; mh += p[2 * GRU + g];
    }
    mz += bg[g]; mr += bg[GRU + g]; mh += bg[2 * GRU + g];
    const float* bgh = bg + 3 * GRU;
    float z = 1.f / (1.f + expf(-(mz + bgh[g])));
    float r = 1.f / (1.f + expf(-(mr + bgh[GRU + g])));
    float hc = tanhf(mh + r * bgh[2 * GRU + g]);
    float st = (1.f - z) * hc;
    state_out[b * GRU + g] = st;
    fc_in[b * (GRU + UNITS) + g] = st;
    fc_in[b * (GRU + UNITS) + GRU + g] = features[b * UNITS + g];
    fc_in[b * (GRU + UNITS) + GRU + 256 + g] = features[b * UNITS + 256 + g];
}

// ---------------- attention score ----------------
__global__ __launch_bounds__(256) void score_k(
    const float* __restrict__ qp, const float* __restrict__ hidproj,
    const float* __restrict__ V, const float* __restrict__ bV,
    float* __restrict__ score)
{
    int bs = blockIdx.x, b = bs >> 6, t = threadIdx.x;
    const float* qrow = qp + bs * UNITS;
    const float* hp = hidproj + b * UNITS;
    float s = 0.f;
    for (int u = t; u < UNITS; u += 256)
        s += tanhf(qrow[u] + hp[u]) * V[u];
    __shared__ float red[256];
    red[t] = s; __syncthreads();
    for (int o = 128; o > 0; o >>= 1) {
        if (t < o) red[t] += red[t + o];
        __syncthreads();
    }
    if (t == 0) score[bs] = red[0] + bV[0];
}

// ---------------- softmax + context + embedding ----------------
__global__ __launch_bounds__(64) void softctx_k(
    const float* __restrict__ score, const float* __restrict__ qs,
    const int* __restrict__ x, const float* __restrict__ E,
    float* __restrict__ weights_out, float* __restrict__ gx)
{
    int b = blockIdx.y, part = blockIdx.x, t = threadIdx.x;
    __shared__ float w[SEQ];
    w[t] = score[b * SEQ + t];
    __syncthreads();
    if (t < 32) {
        float a0 = w[t], a1 = w[t + 32];
        float m = fmaxf(a0, a1);
#pragma unroll
        for (int o = 16; o; o >>= 1) m = fmaxf(m, __shfl_xor_sync(0xffffffff, m, o));
        float e0 = expf(a0 - m), e1 = expf(a1 - m);
        float s = e0 + e1;
#pragma unroll
        for (int o = 16; o; o >>= 1) s += __shfl_xor_sync(0xffffffff, s, o);
        float inv = 1.f / s;
        w[t] = e0 * inv; w[t + 32] = e1 * inv;
    }
    __syncthreads();
    if (part == 0) weights_out[b * SEQ + t] = w[t];
    int e = part * 64 + t;
    float c = 0.f;
#pragma unroll 8
    for (int s2 = 0; s2 < SEQ; s2++)
        c = fmaf(w[s2], qs[(b * SEQ + s2) * EMB + e], c);
    gx[b * 2 * EMB + EMB + e] = c;
    gx[b * 2 * EMB + e] = E[x[b] * EMB + e];
}

// ---------------- launch ----------------
extern "C" void kernel_launch(void* const* d_in, const int* in_sizes, int n_in,
                              void* d_out, int out_size)
{
    const int*   x        = (const int*)  d_in[0];
    const float* qs       = (const float*)d_in[1];
    const float* features = (const float*)d_in[2];
    const float* hidden   = (const float*)d_in[3];
    const float* E        = (const float*)d_in[4];
    const float* W1       = (const float*)d_in[5];
    const float* b1       = (const float*)d_in[6];
    const float* W2       = (const float*)d_in[7];
    const float* b2       = (const float*)d_in[8];
    const float* V        = (const float*)d_in[9];
    const float* bV       = (const float*)d_in[10];
    const float* Kg       = (const float*)d_in[11];
    /* d_in[12] = Ug dead (h0 == 0) */
    const float* bg       = (const float*)d_in[13];
    const float* Wf1      = (const float*)d_in[14];
    const float* bf1      = (const float*)d_in[15];
    const float* Wf2      = (const float*)d_in[16];
    const float* bf2      = (const float*)d_in[17];
    const float* Wo       = (const float*)d_in[18];
    const float* bo       = (const float*)d_in[19];

    float* out = (float*)d_out;
    float* logits      = out;
    float* state_out   = out + BATCH * VOCAB;
    float* weights_out = state_out + BATCH * GRU;

    float *hidproj, *qp, *score, *gx, *fcin, *t1, *t2, *part, *qsdup, *t2dup;
    cudaGetSymbolAddress((void**)&hidproj, g_hidproj);
    cudaGetSymbolAddress((void**)&qp,      g_qp);
    cudaGetSymbolAddress((void**)&score,   g_score);
    cudaGetSymbolAddress((void**)&gx,      g_gx);
    cudaGetSymbolAddress((void**)&fcin,    g_fcin);
    cudaGetSymbolAddress((void**)&t1,      g_t1);
    cudaGetSymbolAddress((void**)&t2,      g_t2);
    cudaGetSymbolAddress((void**)&part,    g_part);
    cudaGetSymbolAddress((void**)&qsdup,   g_qsdup);
    cudaGetSymbolAddress((void**)&t2dup,   g_t2dup);

    cudaFuncSetAttribute(gemm_cp, cudaFuncAttributeMaxDynamicSharedMemorySize, GG_SMEM);

    // 1-2: hidden @ W2 + b2  (K-split 8 -> 128 blocks)
    dense8_ks<<<dim3(UNITS / 256, BATCH / 8, 8), 256, 64 * 10 * 4>>>(
        hidden, W2, part, UNITS, UNITS, 64);
    fin_k<<<BATCH * UNITS / 256, 256>>>(part, b2, hidproj, UNITS, 8);
    // 3: dup2-transpose qs  [4096,256] -> [128][16384]
    dup_k2<<<dim3(EMB / 32, (BATCH * SEQ) / 32), 256>>>(qs, qsdup, BATCH * SEQ, EMB);
    // 4 (PROFILED): qs @ W1 + b1
    gemm_cp<<<dim3(UNITS / 128, (BATCH * SEQ) / 64), 256, GG_SMEM>>>(
        qsdup, W1, b1, qp, BATCH * SEQ, UNITS, EMB);
    // 5-6: score + softmax/context/embed
    score_k<<<BATCH * SEQ, 256>>>(qp, hidproj, V, bV, score);
    softctx_k<<<dim3(4, BATCH), 64>>>(score, qs, x, E, weights_out, gx);
    // 7-8: GRU (K-split 8 -> 192 blocks)
    dense8_ks<<<dim3(3 * GRU / 256, BATCH / 8, 8), 256, 64 * 10 * 4>>>(
        gx, Kg, part, 2 * EMB, 3 * GRU, 64);
    gru_fin<<<BATCH, GRU>>>(part, bg, features, state_out, fcin);
    // 9-12: fc stack (K-split 8 -> 256 blocks each)
    dense8_ks<<<dim3(FC / 256, BATCH / 8, 8), 256, 96 * 10 * 4>>>(
        fcin, Wf1, part, GRU + UNITS, FC, 96);
    fin_k<<<BATCH * FC / 256, 256>>>(part, bf1, t1, FC, 8);
    dense8_ks<<<dim3(FC / 256, BATCH / 8, 8), 256, 128 * 10 * 4>>>(
        t1, Wf2, part, FC, FC, 128);
    fin_k<<<BATCH * FC / 256, 256>>>(part, bf2, t2, FC, 8);
    // 13: dup2-transpose t2  [64,1024] -> [512][256]
    dup_k2<<<dim3(FC / 32, BATCH / 32), 256>>>(t2, t2dup, BATCH, FC);
    // 14: logits GEMM  [64,50000] = t2 @ Wo + bo
    gemm_cp<<<dim3((VOCAB + 127) / 128, 1), 256, GG_SMEM>>>(
        t2dup, Wo, bo, logits, BATCH, VOCAB, FC);
}